// round 10
// baseline (speedup 1.0000x reference)
#include <cuda_runtime.h>

#define NB 4
#define BATCH 1024
#define EPS 1e-5f

// Scratch (no allocations allowed). 16B-aligned for vectorized access.
__device__ __align__(16) float g_psi[BATCH * 16];
__device__ __align__(16) float g_psip[BATCH * 16];
__device__ __align__(16) float g_attn[NB * BATCH * 8];   // [t][j][k]
__device__ __align__(16) float g_ffn[NB * BATCH * 8];    // [t][j][k]

// ---------------- packed f32x2 helpers ----------------
typedef unsigned long long u64;
__device__ __forceinline__ u64 pk(float lo, float hi) {
    u64 r; asm("mov.b64 %0,{%1,%2};" : "=l"(r) : "f"(lo), "f"(hi)); return r;
}
__device__ __forceinline__ void up(u64 v, float& lo, float& hi) {
    asm("mov.b64 {%0,%1},%2;" : "=f"(lo), "=f"(hi) : "l"(v));
}
__device__ __forceinline__ u64 add2(u64 a, u64 b) {
    u64 r; asm("add.rn.f32x2 %0,%1,%2;" : "=l"(r) : "l"(a), "l"(b)); return r;
}
__device__ __forceinline__ u64 mul2(u64 a, u64 b) {
    u64 r; asm("mul.rn.f32x2 %0,%1,%2;" : "=l"(r) : "l"(a), "l"(b)); return r;
}
__device__ __forceinline__ u64 fma2(u64 a, u64 b, u64 c) {
    u64 r; asm("fma.rn.f32x2 %0,%1,%2,%3;" : "=l"(r) : "l"(a), "l"(b), "l"(c)); return r;
}

// Forward CNOT-ladder permutation for n=4: (0,1),(1,2),(2,3),(3,0)
__device__ __forceinline__ int fwd4(int m) {
    int idx = m;
    idx ^= ((idx >> 3) & 1) << 2;
    idx ^= ((idx >> 2) & 1) << 1;
    idx ^= ((idx >> 1) & 1) << 0;
    idx ^= ((idx >> 0) & 1) << 3;
    return idx;
}

// LayerNorm over 8 channels, tree-structured reductions (log-depth latency)
__device__ __forceinline__ void ln8(float h[8], const float* g, const float* b) {
    float m = ((h[0] + h[1]) + (h[2] + h[3])) + ((h[4] + h[5]) + (h[6] + h[7]));
    m *= 0.125f;
    float d0 = h[0] - m, d1 = h[1] - m, d2 = h[2] - m, d3 = h[3] - m;
    float d4 = h[4] - m, d5 = h[5] - m, d6 = h[6] - m, d7 = h[7] - m;
    float v = ((d0 * d0 + d1 * d1) + (d2 * d2 + d3 * d3)) +
              ((d4 * d4 + d5 * d5) + (d6 * d6 + d7 * d7));
    float rs = rsqrtf(v * 0.125f + EPS);
    h[0] = d0 * rs * g[0] + b[0]; h[1] = d1 * rs * g[1] + b[1];
    h[2] = d2 * rs * g[2] + b[2]; h[3] = d3 * rs * g[3] + b[3];
    h[4] = d4 * rs * g[4] + b[4]; h[5] = d5 * rs * g[5] + b[5];
    h[6] = d6 * rs * g[6] + b[6]; h[7] = d7 * rs * g[7] + b[7];
}

// Packed LN for 2 columns, register-lean: g/b streamed one u64 at a time.
__device__ __forceinline__ void ln8p2(u64 h[2][4], const u64* g, const u64* b) {
    u64 rr[2], nm[2];
#pragma unroll
    for (int q = 0; q < 2; q++) {
        u64 s = add2(add2(h[q][0], h[q][1]), add2(h[q][2], h[q][3]));
        u64 qs = mul2(h[q][0], h[q][0]);
        qs = fma2(h[q][1], h[q][1], qs);
        qs = fma2(h[q][2], h[q][2], qs);
        qs = fma2(h[q][3], h[q][3], qs);
        float sl, sh, ql, qh;
        up(s, sl, sh); up(qs, ql, qh);
        float m = (sl + sh) * 0.125f;
        float e2 = (ql + qh) * 0.125f;
        float rs = rsqrtf(fmaf(-m, m, e2) + EPS);
        rr[q] = pk(rs, rs);
        nm[q] = pk(-m, -m);
    }
#pragma unroll
    for (int k = 0; k < 4; k++) {
        u64 gk = g[k], bk = b[k];       // warp-uniform LDS.64 broadcasts
#pragma unroll
        for (int q = 0; q < 2; q++) {
            u64 G = mul2(rr[q], gk);
            u64 C = fma2(nm[q], G, bk);
            h[q][k] = fma2(h[q][k], G, C);
        }
    }
}

// attn[w>=1] = z0*...*zw ; attn[0] = z1*...*z7
__device__ __forceinline__ void attn8(const float z[8], float a[8]) {
    float p = z[0];
#pragma unroll
    for (int w = 1; w < 8; w++) { p *= z[w]; a[w] = p; }
    float q = z[1];
#pragma unroll
    for (int w = 2; w < 8; w++) q *= z[w];
    a[0] = q;
}

__device__ __forceinline__ void psi16(const float* __restrict__ x, int row, float p[16]) {
    float c[4], s[4];
#pragma unroll
    for (int w = 0; w < 4; w++) {
        float hh = 0.5f * x[row * 4 + w];
        c[w] = __cosf(hh); s[w] = __sinf(hh);
    }
#pragma unroll
    for (int m = 0; m < 16; m++) {
        p[m] = (((m >> 3) & 1) ? s[0] : c[0]) * (((m >> 2) & 1) ? s[1] : c[1]) *
               (((m >> 1) & 1) ? s[2] : c[2]) * (((m >> 0) & 1) ? s[3] : c[3]);
    }
}

// ---------------- Fused sequential phase (also initializes out = cls_b) ----------------
__global__ void k_phaseB(const float* __restrict__ x,
                         const float* __restrict__ proj_w, const float* __restrict__ proj_b,
                         const float* __restrict__ rx, const float* __restrict__ ry,
                         const float* __restrict__ ffn_w, const float* __restrict__ ffn_b,
                         const float* __restrict__ ln1_g, const float* __restrict__ ln1_b,
                         const float* __restrict__ ln2_g, const float* __restrict__ ln2_b,
                         const float* __restrict__ cls_b, float* __restrict__ out) {
    __shared__ float sRx[NB * 8], sRy[NB * 8];
    __shared__ float sFw[NB * 64], sFb[NB * 8];
    __shared__ float sL1G[NB * 8], sL1B[NB * 8], sL2G[NB * 8], sL2B[NB * 8];
    __shared__ float sPW[8], sPB[8];
    __shared__ float sA[NB][8][9];
    __shared__ float sF[NB][8][9];

    int tid = threadIdx.x;           // 0..63
    int gid = blockIdx.x * 64 + tid;

    // initialize classifier output with bias (k_final atomically accumulates onto it)
    for (int u = gid; u < BATCH * 10; u += 128 * 64) out[u] = cls_b[u % 10];

    if (tid < NB * 8) {
        sRx[tid] = rx[tid]; sRy[tid] = ry[tid]; sFb[tid] = ffn_b[tid];
        sL1G[tid] = ln1_g[tid]; sL1B[tid] = ln1_b[tid];
        sL2G[tid] = ln2_g[tid]; sL2B[tid] = ln2_b[tid];
    }
    if (tid < 8) { sPW[tid] = proj_w[tid]; sPB[tid] = proj_b[tid]; }
    for (int u = tid; u < NB * 64; u += 64) sFw[u] = ffn_w[u];
    __syncthreads();

    int lane = tid & 31;
    int rowbase = lane & 24;
    const unsigned mask = 0xFFFFFFFFu;

    int r0 = tid >> 3;
    int m = tid & 7;
    int j = gid >> 3;

    float pm[16];
    {
        float t16[16];
        psi16(x, m, t16);
#pragma unroll
        for (int u = 0; u < 16; u++) pm[u] = t16[fwd4(u)];
    }
    float h0[8], h1[8];
    {
        float pj[16];
        psi16(x, r0, pj);
        float d = 0.f;
#pragma unroll
        for (int u = 0; u < 16; u++) d += pj[u] * pm[u];
        float gr = fabsf(d);
#pragma unroll
        for (int k = 0; k < 8; k++) h0[k] = gr * sPW[k] + sPB[k];
    }
    {
        float pj[16];
        psi16(x, j, pj);
        float d = 0.f;
#pragma unroll
        for (int u = 0; u < 16; u++) d += pj[u] * pm[u];
        float gr = fabsf(d);
#pragma unroll
        for (int k = 0; k < 8; k++) h1[k] = gr * sPW[k] + sPB[k];

        if (m == 0) {
            float pp[16];
#pragma unroll
            for (int u = 0; u < 16; u++) pp[u] = pj[fwd4(u)];
            float4* po = (float4*)(g_psi + (size_t)j * 16);
            float4* pq = (float4*)(g_psip + (size_t)j * 16);
#pragma unroll
            for (int q = 0; q < 4; q++) {
                po[q] = make_float4(pj[4 * q], pj[4 * q + 1], pj[4 * q + 2], pj[4 * q + 3]);
                pq[q] = make_float4(pp[4 * q], pp[4 * q + 1], pp[4 * q + 2], pp[4 * q + 3]);
            }
        }
    }

    float cRx[NB], ryv[NB];
#pragma unroll
    for (int t = 0; t < NB; t++) { cRx[t] = __cosf(rx[t * 8 + m]); ryv[t] = ry[t * 8 + m]; }

#pragma unroll
    for (int t = 0; t < NB; t++) {
        float z0 = cRx[t] * __cosf(h0[0]);
        float z1 = cRx[t] * __cosf(h1[0]);
        float zz0[8], zz1[8];
#pragma unroll
        for (int u = 0; u < 8; u++) {
            zz0[u] = __shfl_sync(mask, z0, rowbase | u);
            zz1[u] = __shfl_sync(mask, z1, rowbase | u);
        }
        float a0[8], a1[8];
        attn8(zz0, a0);
        attn8(zz1, a1);
        sA[t][r0][m] = a0[m];
        g_attn[(size_t)t * BATCH * 8 + (size_t)j * 8 + m] = a1[m];
        __syncthreads();

        float av[8];
#pragma unroll
        for (int k = 0; k < 8; k++) av[k] = sA[t][m][k];
#pragma unroll
        for (int k = 0; k < 8; k++) { h0[k] += av[k]; h1[k] += av[k]; }
        ln8(h0, sL1G + t * 8, sL1B + t * 8);
        ln8(h1, sL1G + t * 8, sL1B + t * 8);

        float mv0 = __cosf(h0[0] + ryv[t]); mv0 = mv0 > 0.f ? mv0 : 0.f;
        float mv1 = __cosf(h1[0] + ryv[t]); mv1 = mv1 > 0.f ? mv1 : 0.f;
        float s0 = sFb[t * 8 + m], s1 = s0;
#pragma unroll
        for (int u = 0; u < 8; u++) {
            float w = sFw[t * 64 + m * 8 + u];
            s0 += __shfl_sync(mask, mv0, rowbase | u) * w;
            s1 += __shfl_sync(mask, mv1, rowbase | u) * w;
        }
        sF[t][r0][m] = s0;
        g_ffn[(size_t)t * BATCH * 8 + (size_t)j * 8 + m] = s1;
        __syncthreads();

        float fv[8];
#pragma unroll
        for (int k = 0; k < 8; k++) fv[k] = sF[t][m][k];
#pragma unroll
        for (int k = 0; k < 8; k++) { h0[k] += fv[k]; h1[k] += fv[k]; }
        ln8(h0, sL2G + t * 8, sL2B + t * 8);
        ln8(h1, sL2G + t * 8, sL2B + t * 8);
    }
}

// ---------------- Final sweep: 4 blocks/SM, register-lean (u64 loads, smem acc) ----------------
__global__ void __launch_bounds__(256, 4) k_final(
                        const float* __restrict__ proj_w, const float* __restrict__ proj_b,
                        const float* __restrict__ ln1_g, const float* __restrict__ ln1_b,
                        const float* __restrict__ ln2_g, const float* __restrict__ ln2_b,
                        const float* __restrict__ cls_w, float* __restrict__ out) {
    __shared__ __align__(16) u64 sPsiP[64][8];       // permuted psi, packed pairs
    __shared__ __align__(16) u64 sAttn[NB][64][4];
    __shared__ __align__(16) u64 sFfn[NB][64][4];
    __shared__ __align__(16) u64 sPW[4], sPB[4];
    __shared__ __align__(16) u64 sL1G[NB][4], sL1B[NB][4], sL2G[NB][4], sL2B[NB][4];
    __shared__ float sClsW[10][8];
    __shared__ __align__(16) u64 sAcc[8][32][5];     // per-thread packed acc (padded: 2-way max)
    __shared__ float sRow[32][9];                    // per-row pooled sums (padded)

    int jb = blockIdx.x;            // 16 j-blocks of 64 columns
    int ib = blockIdx.y;            // 32 i-blocks of 32 rows
    int tid = threadIdx.x;          // 256 threads = 8 warps
    int lane = tid & 31, w = tid >> 5;
    int j0 = jb * 64;
    int i = ib * 32 + lane;

    // cooperative u64 tile loads
    {
        const u64* gp = (const u64*)(g_psip + (size_t)j0 * 16);
        ((u64*)sPsiP)[tid] = gp[tid];
        ((u64*)sPsiP)[tid + 256] = gp[tid + 256];
        const u64* ga;
#pragma unroll
        for (int t = 0; t < NB; t++) {
            ga = (const u64*)(g_attn + (size_t)t * BATCH * 8 + j0 * 8);
            ((u64*)&sAttn[t][0][0])[tid] = ga[tid];
            ga = (const u64*)(g_ffn + (size_t)t * BATCH * 8 + j0 * 8);
            ((u64*)&sFfn[t][0][0])[tid] = ga[tid];
        }
    }
    if (tid < 4) { sPW[tid] = ((const u64*)proj_w)[tid]; sPB[tid] = ((const u64*)proj_b)[tid]; }
    if (tid < NB * 4) {
        int t = tid >> 2, k = tid & 3;
        sL1G[t][k] = ((const u64*)ln1_g)[tid];
        sL1B[t][k] = ((const u64*)ln1_b)[tid];
        sL2G[t][k] = ((const u64*)ln2_g)[tid];
        sL2B[t][k] = ((const u64*)ln2_b)[tid];
    }
    if (tid < 80) sClsW[tid >> 3][tid & 7] = cls_w[tid];
#pragma unroll
    for (int k = 0; k < 4; k++) sAcc[w][lane][k] = 0ull;
    __syncthreads();

    u64 psi[8];
    {
        const float4* pp = (const float4*)(g_psi + (size_t)i * 16);
#pragma unroll
        for (int q = 0; q < 4; q++) {
            float4 v = pp[q];
            psi[2 * q] = pk(v.x, v.y);
            psi[2 * q + 1] = pk(v.z, v.w);
        }
    }

#pragma unroll
    for (int pass = 0; pass < 4; pass++) {
        int jcb = w * 8 + pass * 2;         // warp-uniform base column
        u64 h[2][4];

        // gram dot + h init for 2 columns (independent chains)
#pragma unroll
        for (int q = 0; q < 2; q++) {
            const u64* qq = &sPsiP[jcb + q][0];
            u64 dp = mul2(psi[0], qq[0]);
#pragma unroll
            for (int u = 1; u < 8; u++) dp = fma2(psi[u], qq[u], dp);
            float dl, dh;
            up(dp, dl, dh);
            float g = fabsf(dl + dh);
            u64 gg = pk(g, g);
#pragma unroll
            for (int k = 0; k < 4; k++) h[q][k] = fma2(gg, sPW[k], sPB[k]);
        }

#pragma unroll
        for (int t = 0; t < NB; t++) {
#pragma unroll
            for (int k = 0; k < 4; k++) {
                h[0][k] = add2(h[0][k], sAttn[t][jcb][k]);
                h[1][k] = add2(h[1][k], sAttn[t][jcb + 1][k]);
            }
            ln8p2(h, sL1G[t], sL1B[t]);
#pragma unroll
            for (int k = 0; k < 4; k++) {
                h[0][k] = add2(h[0][k], sFfn[t][jcb][k]);
                h[1][k] = add2(h[1][k], sFfn[t][jcb + 1][k]);
            }
            ln8p2(h, sL2G[t], sL2B[t]);
        }

#pragma unroll
        for (int k = 0; k < 4; k++)
            sAcc[w][lane][k] = add2(sAcc[w][lane][k], add2(h[0][k], h[1][k]));
    }

    __syncthreads();
    {
        int il = tid >> 3, k = tid & 7;     // 256 threads = 32 rows x 8 channels
        float s = 0.f;
#pragma unroll
        for (int ww = 0; ww < 8; ww++) s += ((const float*)sAcc[ww][il])[k];
        sRow[il][k] = s;
    }
    __syncthreads();
    {
        int il = tid >> 3, c = tid & 7;     // classifier: rows x classes 0..7 (+8,9)
        int ii = ib * 32 + il;
        float d = 0.f;
#pragma unroll
        for (int k = 0; k < 8; k++) d += sRow[il][k] * sClsW[c][k];
        atomicAdd(&out[ii * 10 + c], d * (1.0f / BATCH));
        if (c < 2) {
            int c1 = c + 8;
            float d1 = 0.f;
#pragma unroll
            for (int k = 0; k < 8; k++) d1 += sRow[il][k] * sClsW[c1][k];
            atomicAdd(&out[ii * 10 + c1], d1 * (1.0f / BATCH));
        }
    }
}

extern "C" void kernel_launch(void* const* d_in, const int* in_sizes, int n_in,
                              void* d_out, int out_size) {
    const float* x      = (const float*)d_in[0];
    const float* proj_w = (const float*)d_in[1];
    const float* proj_b = (const float*)d_in[2];
    const float* rx     = (const float*)d_in[3];
    const float* ry     = (const float*)d_in[4];
    const float* ffn_w  = (const float*)d_in[5];
    const float* ffn_b  = (const float*)d_in[6];
    const float* ln1_g  = (const float*)d_in[7];
    const float* ln1_b  = (const float*)d_in[8];
    const float* ln2_g  = (const float*)d_in[9];
    const float* ln2_b  = (const float*)d_in[10];
    const float* cls_w  = (const float*)d_in[11];
    const float* cls_b  = (const float*)d_in[12];
    float* out = (float*)d_out;

    k_phaseB<<<128, 64>>>(x, proj_w, proj_b, rx, ry, ffn_w, ffn_b,
                          ln1_g, ln1_b, ln2_g, ln2_b, cls_b, out);
    k_final<<<dim3(16, 32), 256>>>(proj_w, proj_b, ln1_g, ln1_b, ln2_g, ln2_b,
                                   cls_w, out);
}

// round 11
// speedup vs baseline: 1.3006x; 1.3006x over previous
#include <cuda_runtime.h>

#define NB 4
#define BATCH 1024
#define EPS 1e-5f

// Scratch (no allocations allowed). 16B-aligned for vectorized access.
__device__ __align__(16) float g_psi[BATCH * 16];
__device__ __align__(16) float g_psip[BATCH * 16];
__device__ __align__(16) float g_attn[NB * BATCH * 8];   // [t][j][k]
__device__ __align__(16) float g_ffn[NB * BATCH * 8];    // [t][j][k]

// ---------------- packed f32x2 helpers ----------------
typedef unsigned long long u64;
__device__ __forceinline__ u64 pk(float lo, float hi) {
    u64 r; asm("mov.b64 %0,{%1,%2};" : "=l"(r) : "f"(lo), "f"(hi)); return r;
}
__device__ __forceinline__ void up(u64 v, float& lo, float& hi) {
    asm("mov.b64 {%0,%1},%2;" : "=f"(lo), "=f"(hi) : "l"(v));
}
__device__ __forceinline__ u64 add2(u64 a, u64 b) {
    u64 r; asm("add.rn.f32x2 %0,%1,%2;" : "=l"(r) : "l"(a), "l"(b)); return r;
}
__device__ __forceinline__ u64 mul2(u64 a, u64 b) {
    u64 r; asm("mul.rn.f32x2 %0,%1,%2;" : "=l"(r) : "l"(a), "l"(b)); return r;
}
__device__ __forceinline__ u64 fma2(u64 a, u64 b, u64 c) {
    u64 r; asm("fma.rn.f32x2 %0,%1,%2,%3;" : "=l"(r) : "l"(a), "l"(b), "l"(c)); return r;
}

// Forward CNOT-ladder permutation for n=4: (0,1),(1,2),(2,3),(3,0)
__device__ __forceinline__ int fwd4(int m) {
    int idx = m;
    idx ^= ((idx >> 3) & 1) << 2;
    idx ^= ((idx >> 2) & 1) << 1;
    idx ^= ((idx >> 1) & 1) << 0;
    idx ^= ((idx >> 0) & 1) << 3;
    return idx;
}

// LayerNorm over 8 channels, tree-structured reductions (log-depth latency)
__device__ __forceinline__ void ln8(float h[8], const float* g, const float* b) {
    float m = ((h[0] + h[1]) + (h[2] + h[3])) + ((h[4] + h[5]) + (h[6] + h[7]));
    m *= 0.125f;
    float d0 = h[0] - m, d1 = h[1] - m, d2 = h[2] - m, d3 = h[3] - m;
    float d4 = h[4] - m, d5 = h[5] - m, d6 = h[6] - m, d7 = h[7] - m;
    float v = ((d0 * d0 + d1 * d1) + (d2 * d2 + d3 * d3)) +
              ((d4 * d4 + d5 * d5) + (d6 * d6 + d7 * d7));
    float rs = rsqrtf(v * 0.125f + EPS);
    h[0] = d0 * rs * g[0] + b[0]; h[1] = d1 * rs * g[1] + b[1];
    h[2] = d2 * rs * g[2] + b[2]; h[3] = d3 * rs * g[3] + b[3];
    h[4] = d4 * rs * g[4] + b[4]; h[5] = d5 * rs * g[5] + b[5];
    h[6] = d6 * rs * g[6] + b[6]; h[7] = d7 * rs * g[7] + b[7];
}

// Packed LN applied to 4 independent columns; gamma/beta loaded ONCE (LDS.128).
__device__ __forceinline__ void ln8p4(u64 h[4][4], const u64* g, const u64* b) {
    ulonglong2 g01 = *(const ulonglong2*)g;
    ulonglong2 g23 = *(const ulonglong2*)(g + 2);
    ulonglong2 b01 = *(const ulonglong2*)b;
    ulonglong2 b23 = *(const ulonglong2*)(b + 2);
    u64 gr[4] = { g01.x, g01.y, g23.x, g23.y };
    u64 br[4] = { b01.x, b01.y, b23.x, b23.y };
    float m[4], rs[4];
#pragma unroll
    for (int q = 0; q < 4; q++) {
        u64 s = add2(add2(h[q][0], h[q][1]), add2(h[q][2], h[q][3]));
        u64 qs = mul2(h[q][0], h[q][0]);
        qs = fma2(h[q][1], h[q][1], qs);
        qs = fma2(h[q][2], h[q][2], qs);
        qs = fma2(h[q][3], h[q][3], qs);
        float sl, sh, ql, qh;
        up(s, sl, sh); up(qs, ql, qh);
        m[q] = (sl + sh) * 0.125f;
        float e2 = (ql + qh) * 0.125f;
        rs[q] = rsqrtf(fmaf(-m[q], m[q], e2) + EPS);
    }
#pragma unroll
    for (int q = 0; q < 4; q++) {
        u64 rr = pk(rs[q], rs[q]), nm = pk(-m[q], -m[q]);
#pragma unroll
        for (int k = 0; k < 4; k++) {
            u64 G = mul2(rr, gr[k]);
            u64 C = fma2(nm, G, br[k]);
            h[q][k] = fma2(h[q][k], G, C);
        }
    }
}

// attn[w>=1] = z0*...*zw ; attn[0] = z1*...*z7
__device__ __forceinline__ void attn8(const float z[8], float a[8]) {
    float p = z[0];
#pragma unroll
    for (int w = 1; w < 8; w++) { p *= z[w]; a[w] = p; }
    float q = z[1];
#pragma unroll
    for (int w = 2; w < 8; w++) q *= z[w];
    a[0] = q;
}

__device__ __forceinline__ void psi16(const float* __restrict__ x, int row, float p[16]) {
    float c[4], s[4];
#pragma unroll
    for (int w = 0; w < 4; w++) {
        float hh = 0.5f * x[row * 4 + w];
        c[w] = __cosf(hh); s[w] = __sinf(hh);
    }
#pragma unroll
    for (int m = 0; m < 16; m++) {
        p[m] = (((m >> 3) & 1) ? s[0] : c[0]) * (((m >> 2) & 1) ? s[1] : c[1]) *
               (((m >> 1) & 1) ? s[2] : c[2]) * (((m >> 0) & 1) ? s[3] : c[3]);
    }
}

// ---------------- Fused sequential phase (also initializes out = cls_b) ----------------
__global__ void k_phaseB(const float* __restrict__ x,
                         const float* __restrict__ proj_w, const float* __restrict__ proj_b,
                         const float* __restrict__ rx, const float* __restrict__ ry,
                         const float* __restrict__ ffn_w, const float* __restrict__ ffn_b,
                         const float* __restrict__ ln1_g, const float* __restrict__ ln1_b,
                         const float* __restrict__ ln2_g, const float* __restrict__ ln2_b,
                         const float* __restrict__ cls_b, float* __restrict__ out) {
    __shared__ float sRx[NB * 8], sRy[NB * 8];
    __shared__ float sFw[NB * 64], sFb[NB * 8];
    __shared__ float sL1G[NB * 8], sL1B[NB * 8], sL2G[NB * 8], sL2B[NB * 8];
    __shared__ float sPW[8], sPB[8];
    __shared__ float sA[NB][8][9];
    __shared__ float sF[NB][8][9];

    int tid = threadIdx.x;           // 0..63
    int gid = blockIdx.x * 64 + tid;

    // initialize classifier output with bias (k_final atomically accumulates onto it)
    for (int u = gid; u < BATCH * 10; u += 128 * 64) out[u] = cls_b[u % 10];

    if (tid < NB * 8) {
        sRx[tid] = rx[tid]; sRy[tid] = ry[tid]; sFb[tid] = ffn_b[tid];
        sL1G[tid] = ln1_g[tid]; sL1B[tid] = ln1_b[tid];
        sL2G[tid] = ln2_g[tid]; sL2B[tid] = ln2_b[tid];
    }
    if (tid < 8) { sPW[tid] = proj_w[tid]; sPB[tid] = proj_b[tid]; }
    for (int u = tid; u < NB * 64; u += 64) sFw[u] = ffn_w[u];
    __syncthreads();

    int lane = tid & 31;
    int rowbase = lane & 24;
    const unsigned mask = 0xFFFFFFFFu;

    int r0 = tid >> 3;
    int m = tid & 7;
    int j = gid >> 3;

    float pm[16];
    {
        float t16[16];
        psi16(x, m, t16);
#pragma unroll
        for (int u = 0; u < 16; u++) pm[u] = t16[fwd4(u)];
    }
    float h0[8], h1[8];
    {
        float pj[16];
        psi16(x, r0, pj);
        float d = 0.f;
#pragma unroll
        for (int u = 0; u < 16; u++) d += pj[u] * pm[u];
        float gr = fabsf(d);
#pragma unroll
        for (int k = 0; k < 8; k++) h0[k] = gr * sPW[k] + sPB[k];
    }
    {
        float pj[16];
        psi16(x, j, pj);
        float d = 0.f;
#pragma unroll
        for (int u = 0; u < 16; u++) d += pj[u] * pm[u];
        float gr = fabsf(d);
#pragma unroll
        for (int k = 0; k < 8; k++) h1[k] = gr * sPW[k] + sPB[k];

        if (m == 0) {
            float pp[16];
#pragma unroll
            for (int u = 0; u < 16; u++) pp[u] = pj[fwd4(u)];
            float4* po = (float4*)(g_psi + (size_t)j * 16);
            float4* pq = (float4*)(g_psip + (size_t)j * 16);
#pragma unroll
            for (int q = 0; q < 4; q++) {
                po[q] = make_float4(pj[4 * q], pj[4 * q + 1], pj[4 * q + 2], pj[4 * q + 3]);
                pq[q] = make_float4(pp[4 * q], pp[4 * q + 1], pp[4 * q + 2], pp[4 * q + 3]);
            }
        }
    }

    float cRx[NB], ryv[NB];
#pragma unroll
    for (int t = 0; t < NB; t++) { cRx[t] = __cosf(rx[t * 8 + m]); ryv[t] = ry[t * 8 + m]; }

#pragma unroll
    for (int t = 0; t < NB; t++) {
        float z0 = cRx[t] * __cosf(h0[0]);
        float z1 = cRx[t] * __cosf(h1[0]);
        float zz0[8], zz1[8];
#pragma unroll
        for (int u = 0; u < 8; u++) {
            zz0[u] = __shfl_sync(mask, z0, rowbase | u);
            zz1[u] = __shfl_sync(mask, z1, rowbase | u);
        }
        float a0[8], a1[8];
        attn8(zz0, a0);
        attn8(zz1, a1);
        sA[t][r0][m] = a0[m];
        g_attn[(size_t)t * BATCH * 8 + (size_t)j * 8 + m] = a1[m];
        __syncthreads();

        float av[8];
#pragma unroll
        for (int k = 0; k < 8; k++) av[k] = sA[t][m][k];
#pragma unroll
        for (int k = 0; k < 8; k++) { h0[k] += av[k]; h1[k] += av[k]; }
        ln8(h0, sL1G + t * 8, sL1B + t * 8);
        ln8(h1, sL1G + t * 8, sL1B + t * 8);

        float mv0 = __cosf(h0[0] + ryv[t]); mv0 = mv0 > 0.f ? mv0 : 0.f;
        float mv1 = __cosf(h1[0] + ryv[t]); mv1 = mv1 > 0.f ? mv1 : 0.f;
        float s0 = sFb[t * 8 + m], s1 = s0;
#pragma unroll
        for (int u = 0; u < 8; u++) {
            float w = sFw[t * 64 + m * 8 + u];
            s0 += __shfl_sync(mask, mv0, rowbase | u) * w;
            s1 += __shfl_sync(mask, mv1, rowbase | u) * w;
        }
        sF[t][r0][m] = s0;
        g_ffn[(size_t)t * BATCH * 8 + (size_t)j * 8 + m] = s1;
        __syncthreads();

        float fv[8];
#pragma unroll
        for (int k = 0; k < 8; k++) fv[k] = sF[t][m][k];
#pragma unroll
        for (int k = 0; k < 8; k++) { h0[k] += fv[k]; h1[k] += fv[k]; }
        ln8(h0, sL2G + t * 8, sL2B + t * 8);
        ln8(h1, sL2G + t * 8, sL2B + t * 8);
    }
}

// ---------------- Final sweep: R8 inner math, 128-thread blocks, 1024-block balanced grid ----------------
__global__ void __launch_bounds__(128, 6) k_final(
                        const float* __restrict__ proj_w, const float* __restrict__ proj_b,
                        const float* __restrict__ ln1_g, const float* __restrict__ ln1_b,
                        const float* __restrict__ ln2_g, const float* __restrict__ ln2_b,
                        const float* __restrict__ cls_w, float* __restrict__ out) {
    __shared__ __align__(16) u64 sPsiP[32][8];       // permuted psi, packed pairs (32 cols)
    __shared__ __align__(16) u64 sAttn[NB][32][4];
    __shared__ __align__(16) u64 sFfn[NB][32][4];
    __shared__ __align__(16) u64 sPW[4], sPB[4];
    __shared__ __align__(16) u64 sL1G[NB][4], sL1B[NB][4], sL2G[NB][4], sL2B[NB][4];
    __shared__ float sClsW[10][8];
    __shared__ float sRed[4][32][8];
    __shared__ float sRow[32][9];

    int jb = blockIdx.x;            // 32 j-blocks of 32 columns
    int ib = blockIdx.y;            // 32 i-blocks of 32 rows
    int tid = threadIdx.x;          // 128 threads = 4 warps
    int lane = tid & 31, w = tid >> 5;
    int j0 = jb * 32;
    int i = ib * 32 + lane;

    // cooperative 128-bit tile loads
    {
        const ulonglong2* gp = (const ulonglong2*)(g_psip + (size_t)j0 * 16);
        ((ulonglong2*)sPsiP)[tid] = gp[tid];                       // 128 x 16B = psip tile
        for (int u = tid; u < NB * 64; u += 128) {
            int t = u >> 6, r = u & 63;
            ((ulonglong2*)&sAttn[t][0][0])[r] =
                ((const ulonglong2*)(g_attn + (size_t)t * BATCH * 8 + j0 * 8))[r];
            ((ulonglong2*)&sFfn[t][0][0])[r] =
                ((const ulonglong2*)(g_ffn + (size_t)t * BATCH * 8 + j0 * 8))[r];
        }
    }
    if (tid < 4) { sPW[tid] = ((const u64*)proj_w)[tid]; sPB[tid] = ((const u64*)proj_b)[tid]; }
    if (tid < NB * 4) {
        int t = tid >> 2, k = tid & 3;
        sL1G[t][k] = ((const u64*)ln1_g)[tid];
        sL1B[t][k] = ((const u64*)ln1_b)[tid];
        sL2G[t][k] = ((const u64*)ln2_g)[tid];
        sL2B[t][k] = ((const u64*)ln2_b)[tid];
    }
    if (tid < 80) sClsW[tid >> 3][tid & 7] = cls_w[tid];
    __syncthreads();

    u64 psi[8];
    {
        const float4* pp = (const float4*)(g_psi + (size_t)i * 16);
#pragma unroll
        for (int q = 0; q < 4; q++) {
            float4 v = pp[q];
            psi[2 * q] = pk(v.x, v.y);
            psi[2 * q + 1] = pk(v.z, v.w);
        }
    }

    u64 acc[4];
#pragma unroll
    for (int k = 0; k < 4; k++) acc[k] = 0ull;

#pragma unroll
    for (int pass = 0; pass < 2; pass++) {
        int jcb = w * 8 + pass * 4;         // warp-uniform base column (4 warps x 8 cols = 32)
        u64 h[4][4];

        // gram dot + h init for 4 columns (independent chains)
        {
            ulonglong2 pw01 = *(const ulonglong2*)&sPW[0];
            ulonglong2 pw23 = *(const ulonglong2*)&sPW[2];
            ulonglong2 pb01 = *(const ulonglong2*)&sPB[0];
            ulonglong2 pb23 = *(const ulonglong2*)&sPB[2];
#pragma unroll
            for (int q = 0; q < 4; q++) {
                const u64* qq = &sPsiP[jcb + q][0];
                ulonglong2 q0 = *(const ulonglong2*)qq;
                ulonglong2 q1 = *(const ulonglong2*)(qq + 2);
                ulonglong2 q2 = *(const ulonglong2*)(qq + 4);
                ulonglong2 q3 = *(const ulonglong2*)(qq + 6);
                u64 dp = mul2(psi[0], q0.x);
                dp = fma2(psi[1], q0.y, dp);
                dp = fma2(psi[2], q1.x, dp);
                dp = fma2(psi[3], q1.y, dp);
                dp = fma2(psi[4], q2.x, dp);
                dp = fma2(psi[5], q2.y, dp);
                dp = fma2(psi[6], q3.x, dp);
                dp = fma2(psi[7], q3.y, dp);
                float dl, dh;
                up(dp, dl, dh);
                float g = fabsf(dl + dh);
                u64 gg = pk(g, g);
                h[q][0] = fma2(gg, pw01.x, pb01.x);
                h[q][1] = fma2(gg, pw01.y, pb01.y);
                h[q][2] = fma2(gg, pw23.x, pb23.x);
                h[q][3] = fma2(gg, pw23.y, pb23.y);
            }
        }

#pragma unroll
        for (int t = 0; t < NB; t++) {
#pragma unroll
            for (int q = 0; q < 4; q++) {
                const u64* ap = &sAttn[t][jcb + q][0];
                ulonglong2 a01 = *(const ulonglong2*)ap;
                ulonglong2 a23 = *(const ulonglong2*)(ap + 2);
                h[q][0] = add2(h[q][0], a01.x);
                h[q][1] = add2(h[q][1], a01.y);
                h[q][2] = add2(h[q][2], a23.x);
                h[q][3] = add2(h[q][3], a23.y);
            }
            ln8p4(h, sL1G[t], sL1B[t]);
#pragma unroll
            for (int q = 0; q < 4; q++) {
                const u64* fp = &sFfn[t][jcb + q][0];
                ulonglong2 f01 = *(const ulonglong2*)fp;
                ulonglong2 f23 = *(const ulonglong2*)(fp + 2);
                h[q][0] = add2(h[q][0], f01.x);
                h[q][1] = add2(h[q][1], f01.y);
                h[q][2] = add2(h[q][2], f23.x);
                h[q][3] = add2(h[q][3], f23.y);
            }
            ln8p4(h, sL2G[t], sL2B[t]);
        }

#pragma unroll
        for (int k = 0; k < 4; k++)
            acc[k] = add2(acc[k], add2(add2(h[0][k], h[1][k]), add2(h[2][k], h[3][k])));
    }

#pragma unroll
    for (int k = 0; k < 4; k++)
        up(acc[k], sRed[w][lane][2 * k], sRed[w][lane][2 * k + 1]);
    __syncthreads();
    {
        int il = tid >> 2, p = tid & 3;     // 128 threads = 32 rows x 4; 2 channels each
#pragma unroll
        for (int kk = 0; kk < 2; kk++) {
            int k = p * 2 + kk;
            float s = 0.f;
#pragma unroll
            for (int ww = 0; ww < 4; ww++) s += sRed[ww][il][k];
            sRow[il][k] = s;
        }
    }
    __syncthreads();
    {
        int il = tid >> 2, p = tid & 3;     // classifier: 32 rows x 4 threads, classes p,p+4,(p+8)
        int ii = ib * 32 + il;
        for (int c = p; c < 10; c += 4) {
            float d = 0.f;
#pragma unroll
            for (int k = 0; k < 8; k++) d += sRow[il][k] * sClsW[c][k];
            atomicAdd(&out[ii * 10 + c], d * (1.0f / BATCH));
        }
    }
}

extern "C" void kernel_launch(void* const* d_in, const int* in_sizes, int n_in,
                              void* d_out, int out_size) {
    const float* x      = (const float*)d_in[0];
    const float* proj_w = (const float*)d_in[1];
    const float* proj_b = (const float*)d_in[2];
    const float* rx     = (const float*)d_in[3];
    const float* ry     = (const float*)d_in[4];
    const float* ffn_w  = (const float*)d_in[5];
    const float* ffn_b  = (const float*)d_in[6];
    const float* ln1_g  = (const float*)d_in[7];
    const float* ln1_b  = (const float*)d_in[8];
    const float* ln2_g  = (const float*)d_in[9];
    const float* ln2_b  = (const float*)d_in[10];
    const float* cls_w  = (const float*)d_in[11];
    const float* cls_b  = (const float*)d_in[12];
    float* out = (float*)d_out;

    k_phaseB<<<128, 64>>>(x, proj_w, proj_b, rx, ry, ffn_w, ffn_b,
                          ln1_g, ln1_b, ln2_g, ln2_b, cls_b, out);
    k_final<<<dim3(32, 32), 128>>>(proj_w, proj_b, ln1_g, ln1_b, ln2_g, ln2_b,
                                   cls_w, out);
}

// round 12
// speedup vs baseline: 1.8444x; 1.4181x over previous
#include <cuda_runtime.h>

#define NB 4
#define BATCH 1024
#define EPS 1e-5f

// Scratch (no allocations allowed). 16B-aligned for vectorized access.
__device__ __align__(16) float g_psi[BATCH * 16];
__device__ __align__(16) float g_psip[BATCH * 16];
__device__ __align__(16) float g_attn[NB * BATCH * 8];   // [t][j][k]
__device__ __align__(16) float g_ffn[NB * BATCH * 8];    // [t][j][k]

// ---------------- packed f32x2 helpers ----------------
typedef unsigned long long u64;
__device__ __forceinline__ u64 pk(float lo, float hi) {
    u64 r; asm("mov.b64 %0,{%1,%2};" : "=l"(r) : "f"(lo), "f"(hi)); return r;
}
__device__ __forceinline__ void up(u64 v, float& lo, float& hi) {
    asm("mov.b64 {%0,%1},%2;" : "=f"(lo), "=f"(hi) : "l"(v));
}
__device__ __forceinline__ u64 add2(u64 a, u64 b) {
    u64 r; asm("add.rn.f32x2 %0,%1,%2;" : "=l"(r) : "l"(a), "l"(b)); return r;
}
__device__ __forceinline__ u64 mul2(u64 a, u64 b) {
    u64 r; asm("mul.rn.f32x2 %0,%1,%2;" : "=l"(r) : "l"(a), "l"(b)); return r;
}
__device__ __forceinline__ u64 fma2(u64 a, u64 b, u64 c) {
    u64 r; asm("fma.rn.f32x2 %0,%1,%2,%3;" : "=l"(r) : "l"(a), "l"(b), "l"(c)); return r;
}

// Forward CNOT-ladder permutation for n=4: (0,1),(1,2),(2,3),(3,0)
__device__ __forceinline__ int fwd4(int m) {
    int idx = m;
    idx ^= ((idx >> 3) & 1) << 2;
    idx ^= ((idx >> 2) & 1) << 1;
    idx ^= ((idx >> 1) & 1) << 0;
    idx ^= ((idx >> 0) & 1) << 3;
    return idx;
}

// LayerNorm over 8 channels, tree-structured reductions (log-depth latency)
__device__ __forceinline__ void ln8(float h[8], const float* g, const float* b) {
    float m = ((h[0] + h[1]) + (h[2] + h[3])) + ((h[4] + h[5]) + (h[6] + h[7]));
    m *= 0.125f;
    float d0 = h[0] - m, d1 = h[1] - m, d2 = h[2] - m, d3 = h[3] - m;
    float d4 = h[4] - m, d5 = h[5] - m, d6 = h[6] - m, d7 = h[7] - m;
    float v = ((d0 * d0 + d1 * d1) + (d2 * d2 + d3 * d3)) +
              ((d4 * d4 + d5 * d5) + (d6 * d6 + d7 * d7));
    float rs = rsqrtf(v * 0.125f + EPS);
    h[0] = d0 * rs * g[0] + b[0]; h[1] = d1 * rs * g[1] + b[1];
    h[2] = d2 * rs * g[2] + b[2]; h[3] = d3 * rs * g[3] + b[3];
    h[4] = d4 * rs * g[4] + b[4]; h[5] = d5 * rs * g[5] + b[5];
    h[6] = d6 * rs * g[6] + b[6]; h[7] = d7 * rs * g[7] + b[7];
}

// Packed LN for 4 columns. FAST path: gamma==1, beta==0 (verified at runtime).
template <bool FAST>
__device__ __forceinline__ void ln8p4_t(u64 h[4][4], const u64* g, const u64* b) {
    u64 rr[4], nmr[4];
#pragma unroll
    for (int q = 0; q < 4; q++) {
        u64 s = add2(add2(h[q][0], h[q][1]), add2(h[q][2], h[q][3]));
        u64 qs = mul2(h[q][0], h[q][0]);
        qs = fma2(h[q][1], h[q][1], qs);
        qs = fma2(h[q][2], h[q][2], qs);
        qs = fma2(h[q][3], h[q][3], qs);
        float sl, sh, ql, qh;
        up(s, sl, sh); up(qs, ql, qh);
        float m = (sl + sh) * 0.125f;
        float e2 = (ql + qh) * 0.125f;
        float rs = rsqrtf(fmaf(-m, m, e2) + EPS);
        float nm = -m * rs;
        rr[q] = pk(rs, rs);
        nmr[q] = pk(nm, nm);
    }
    if (FAST) {
#pragma unroll
        for (int q = 0; q < 4; q++)
#pragma unroll
            for (int k = 0; k < 4; k++)
                h[q][k] = fma2(h[q][k], rr[q], nmr[q]);
    } else {
        ulonglong2 g01 = *(const ulonglong2*)g;
        ulonglong2 g23 = *(const ulonglong2*)(g + 2);
        ulonglong2 b01 = *(const ulonglong2*)b;
        ulonglong2 b23 = *(const ulonglong2*)(b + 2);
        u64 gr[4] = { g01.x, g01.y, g23.x, g23.y };
        u64 br[4] = { b01.x, b01.y, b23.x, b23.y };
#pragma unroll
        for (int q = 0; q < 4; q++)
#pragma unroll
            for (int k = 0; k < 4; k++) {
                u64 t = fma2(h[q][k], rr[q], nmr[q]);
                h[q][k] = fma2(t, gr[k], br[k]);
            }
    }
}

// attn[w>=1] = z0*...*zw ; attn[0] = z1*...*z7
__device__ __forceinline__ void attn8(const float z[8], float a[8]) {
    float p = z[0];
#pragma unroll
    for (int w = 1; w < 8; w++) { p *= z[w]; a[w] = p; }
    float q = z[1];
#pragma unroll
    for (int w = 2; w < 8; w++) q *= z[w];
    a[0] = q;
}

__device__ __forceinline__ void psi16(const float* __restrict__ x, int row, float p[16]) {
    float c[4], s[4];
#pragma unroll
    for (int w = 0; w < 4; w++) {
        float hh = 0.5f * x[row * 4 + w];
        c[w] = __cosf(hh); s[w] = __sinf(hh);
    }
#pragma unroll
    for (int m = 0; m < 16; m++) {
        p[m] = (((m >> 3) & 1) ? s[0] : c[0]) * (((m >> 2) & 1) ? s[1] : c[1]) *
               (((m >> 1) & 1) ? s[2] : c[2]) * (((m >> 0) & 1) ? s[3] : c[3]);
    }
}

// ---------------- Fused sequential phase (also initializes out = cls_b) ----------------
__global__ void k_phaseB(const float* __restrict__ x,
                         const float* __restrict__ proj_w, const float* __restrict__ proj_b,
                         const float* __restrict__ rx, const float* __restrict__ ry,
                         const float* __restrict__ ffn_w, const float* __restrict__ ffn_b,
                         const float* __restrict__ ln1_g, const float* __restrict__ ln1_b,
                         const float* __restrict__ ln2_g, const float* __restrict__ ln2_b,
                         const float* __restrict__ cls_b, float* __restrict__ out) {
    __shared__ float sRx[NB * 8], sRy[NB * 8];
    __shared__ float sFw[NB * 64], sFb[NB * 8];
    __shared__ float sL1G[NB * 8], sL1B[NB * 8], sL2G[NB * 8], sL2B[NB * 8];
    __shared__ float sPW[8], sPB[8];
    __shared__ float sA[NB][8][9];
    __shared__ float sF[NB][8][9];

    int tid = threadIdx.x;           // 0..63
    int gid = blockIdx.x * 64 + tid;

    // initialize classifier output with bias (k_final atomically accumulates onto it)
    for (int u = gid; u < BATCH * 10; u += 128 * 64) out[u] = cls_b[u % 10];

    if (tid < NB * 8) {
        sRx[tid] = rx[tid]; sRy[tid] = ry[tid]; sFb[tid] = ffn_b[tid];
        sL1G[tid] = ln1_g[tid]; sL1B[tid] = ln1_b[tid];
        sL2G[tid] = ln2_g[tid]; sL2B[tid] = ln2_b[tid];
    }
    if (tid < 8) { sPW[tid] = proj_w[tid]; sPB[tid] = proj_b[tid]; }
    for (int u = tid; u < NB * 64; u += 64) sFw[u] = ffn_w[u];
    __syncthreads();

    int lane = tid & 31;
    int rowbase = lane & 24;
    const unsigned mask = 0xFFFFFFFFu;

    int r0 = tid >> 3;
    int m = tid & 7;
    int j = gid >> 3;

    float pm[16];
    {
        float t16[16];
        psi16(x, m, t16);
#pragma unroll
        for (int u = 0; u < 16; u++) pm[u] = t16[fwd4(u)];
    }
    float h0[8], h1[8];
    {
        float pj[16];
        psi16(x, r0, pj);
        float d = 0.f;
#pragma unroll
        for (int u = 0; u < 16; u++) d += pj[u] * pm[u];
        float gr = fabsf(d);
#pragma unroll
        for (int k = 0; k < 8; k++) h0[k] = gr * sPW[k] + sPB[k];
    }
    {
        float pj[16];
        psi16(x, j, pj);
        float d = 0.f;
#pragma unroll
        for (int u = 0; u < 16; u++) d += pj[u] * pm[u];
        float gr = fabsf(d);
#pragma unroll
        for (int k = 0; k < 8; k++) h1[k] = gr * sPW[k] + sPB[k];

        if (m == 0) {
            float pp[16];
#pragma unroll
            for (int u = 0; u < 16; u++) pp[u] = pj[fwd4(u)];
            float4* po = (float4*)(g_psi + (size_t)j * 16);
            float4* pq = (float4*)(g_psip + (size_t)j * 16);
#pragma unroll
            for (int q = 0; q < 4; q++) {
                po[q] = make_float4(pj[4 * q], pj[4 * q + 1], pj[4 * q + 2], pj[4 * q + 3]);
                pq[q] = make_float4(pp[4 * q], pp[4 * q + 1], pp[4 * q + 2], pp[4 * q + 3]);
            }
        }
    }

    float cRx[NB], ryv[NB];
#pragma unroll
    for (int t = 0; t < NB; t++) { cRx[t] = __cosf(rx[t * 8 + m]); ryv[t] = ry[t * 8 + m]; }

#pragma unroll
    for (int t = 0; t < NB; t++) {
        float z0 = cRx[t] * __cosf(h0[0]);
        float z1 = cRx[t] * __cosf(h1[0]);
        float zz0[8], zz1[8];
#pragma unroll
        for (int u = 0; u < 8; u++) {
            zz0[u] = __shfl_sync(mask, z0, rowbase | u);
            zz1[u] = __shfl_sync(mask, z1, rowbase | u);
        }
        float a0[8], a1[8];
        attn8(zz0, a0);
        attn8(zz1, a1);
        sA[t][r0][m] = a0[m];
        g_attn[(size_t)t * BATCH * 8 + (size_t)j * 8 + m] = a1[m];
        __syncthreads();

        float av[8];
#pragma unroll
        for (int k = 0; k < 8; k++) av[k] = sA[t][m][k];
#pragma unroll
        for (int k = 0; k < 8; k++) { h0[k] += av[k]; h1[k] += av[k]; }
        ln8(h0, sL1G + t * 8, sL1B + t * 8);
        ln8(h1, sL1G + t * 8, sL1B + t * 8);

        float mv0 = __cosf(h0[0] + ryv[t]); mv0 = mv0 > 0.f ? mv0 : 0.f;
        float mv1 = __cosf(h1[0] + ryv[t]); mv1 = mv1 > 0.f ? mv1 : 0.f;
        float s0 = sFb[t * 8 + m], s1 = s0;
#pragma unroll
        for (int u = 0; u < 8; u++) {
            float w = sFw[t * 64 + m * 8 + u];
            s0 += __shfl_sync(mask, mv0, rowbase | u) * w;
            s1 += __shfl_sync(mask, mv1, rowbase | u) * w;
        }
        sF[t][r0][m] = s0;
        g_ffn[(size_t)t * BATCH * 8 + (size_t)j * 8 + m] = s1;
        __syncthreads();

        float fv[8];
#pragma unroll
        for (int k = 0; k < 8; k++) fv[k] = sF[t][m][k];
#pragma unroll
        for (int k = 0; k < 8; k++) { h0[k] += fv[k]; h1[k] += fv[k]; }
        ln8(h0, sL2G + t * 8, sL2B + t * 8);
        ln8(h1, sL2G + t * 8, sL2B + t * 8);
    }
}

// ---------------- k_final mainloop (templated on LN fast path) ----------------
template <bool FAST>
__device__ __forceinline__ void sweep(
    const u64 (*sPsiP)[8], const u64 (*sAttn)[32][4], const u64 (*sFfn)[32][4],
    const u64* sPW, const u64* sPB,
    const u64 (*sL1G)[4], const u64 (*sL1B)[4],
    const u64 (*sL2G)[4], const u64 (*sL2B)[4],
    const u64 psi[8], u64 acc[4], int w) {
#pragma unroll
    for (int pass = 0; pass < 2; pass++) {
        int jcb = w * 8 + pass * 4;         // warp-uniform base column (4 warps x 8 cols = 32)
        u64 h[4][4];

        // gram dot + h init for 4 columns (independent chains)
        {
            ulonglong2 pw01 = *(const ulonglong2*)&sPW[0];
            ulonglong2 pw23 = *(const ulonglong2*)&sPW[2];
            ulonglong2 pb01 = *(const ulonglong2*)&sPB[0];
            ulonglong2 pb23 = *(const ulonglong2*)&sPB[2];
#pragma unroll
            for (int q = 0; q < 4; q++) {
                const u64* qq = &sPsiP[jcb + q][0];
                ulonglong2 q0 = *(const ulonglong2*)qq;
                ulonglong2 q1 = *(const ulonglong2*)(qq + 2);
                ulonglong2 q2 = *(const ulonglong2*)(qq + 4);
                ulonglong2 q3 = *(const ulonglong2*)(qq + 6);
                u64 dp = mul2(psi[0], q0.x);
                dp = fma2(psi[1], q0.y, dp);
                dp = fma2(psi[2], q1.x, dp);
                dp = fma2(psi[3], q1.y, dp);
                dp = fma2(psi[4], q2.x, dp);
                dp = fma2(psi[5], q2.y, dp);
                dp = fma2(psi[6], q3.x, dp);
                dp = fma2(psi[7], q3.y, dp);
                float dl, dh;
                up(dp, dl, dh);
                float g = fabsf(dl + dh);
                u64 gg = pk(g, g);
                h[q][0] = fma2(gg, pw01.x, pb01.x);
                h[q][1] = fma2(gg, pw01.y, pb01.y);
                h[q][2] = fma2(gg, pw23.x, pb23.x);
                h[q][3] = fma2(gg, pw23.y, pb23.y);
            }
        }

#pragma unroll
        for (int t = 0; t < NB; t++) {
#pragma unroll
            for (int q = 0; q < 4; q++) {
                const u64* ap = &sAttn[t][jcb + q][0];
                ulonglong2 a01 = *(const ulonglong2*)ap;
                ulonglong2 a23 = *(const ulonglong2*)(ap + 2);
                h[q][0] = add2(h[q][0], a01.x);
                h[q][1] = add2(h[q][1], a01.y);
                h[q][2] = add2(h[q][2], a23.x);
                h[q][3] = add2(h[q][3], a23.y);
            }
            ln8p4_t<FAST>(h, sL1G[t], sL1B[t]);
#pragma unroll
            for (int q = 0; q < 4; q++) {
                const u64* fp = &sFfn[t][jcb + q][0];
                ulonglong2 f01 = *(const ulonglong2*)fp;
                ulonglong2 f23 = *(const ulonglong2*)(fp + 2);
                h[q][0] = add2(h[q][0], f01.x);
                h[q][1] = add2(h[q][1], f01.y);
                h[q][2] = add2(h[q][2], f23.x);
                h[q][3] = add2(h[q][3], f23.y);
            }
            ln8p4_t<FAST>(h, sL2G[t], sL2B[t]);
        }

#pragma unroll
        for (int k = 0; k < 4; k++)
            acc[k] = add2(acc[k], add2(add2(h[0][k], h[1][k]), add2(h[2][k], h[3][k])));
    }
}

// ---------------- Final sweep: 128-thread blocks, 1024-block balanced grid ----------------
__global__ void __launch_bounds__(128, 6) k_final(
                        const float* __restrict__ proj_w, const float* __restrict__ proj_b,
                        const float* __restrict__ ln1_g, const float* __restrict__ ln1_b,
                        const float* __restrict__ ln2_g, const float* __restrict__ ln2_b,
                        const float* __restrict__ cls_w, float* __restrict__ out) {
    __shared__ __align__(16) u64 sPsiP[32][8];       // permuted psi, packed pairs (32 cols)
    __shared__ __align__(16) u64 sAttn[NB][32][4];
    __shared__ __align__(16) u64 sFfn[NB][32][4];
    __shared__ __align__(16) u64 sPW[4], sPB[4];
    __shared__ __align__(16) u64 sL1G[NB][4], sL1B[NB][4], sL2G[NB][4], sL2B[NB][4];
    __shared__ float sClsW[10][8];
    __shared__ float sRed[4][32][8];
    __shared__ float sRow[32][9];
    __shared__ int sFast;

    int jb = blockIdx.x;            // 32 j-blocks of 32 columns
    int ib = blockIdx.y;            // 32 i-blocks of 32 rows
    int tid = threadIdx.x;          // 128 threads = 4 warps
    int lane = tid & 31, w = tid >> 5;
    int j0 = jb * 32;
    int i = ib * 32 + lane;

    // cooperative 128-bit tile loads
    {
        const ulonglong2* gp = (const ulonglong2*)(g_psip + (size_t)j0 * 16);
        ((ulonglong2*)sPsiP)[tid] = gp[tid];                       // 128 x 16B = psip tile
        for (int u = tid; u < NB * 64; u += 128) {
            int t = u >> 6, r = u & 63;
            ((ulonglong2*)&sAttn[t][0][0])[r] =
                ((const ulonglong2*)(g_attn + (size_t)t * BATCH * 8 + j0 * 8))[r];
            ((ulonglong2*)&sFfn[t][0][0])[r] =
                ((const ulonglong2*)(g_ffn + (size_t)t * BATCH * 8 + j0 * 8))[r];
        }
    }
    if (tid < 4) { sPW[tid] = ((const u64*)proj_w)[tid]; sPB[tid] = ((const u64*)proj_b)[tid]; }
    if (tid < NB * 4) {
        int t = tid >> 2, k = tid & 3;
        sL1G[t][k] = ((const u64*)ln1_g)[tid];
        sL1B[t][k] = ((const u64*)ln1_b)[tid];
        sL2G[t][k] = ((const u64*)ln2_g)[tid];
        sL2B[t][k] = ((const u64*)ln2_b)[tid];
    }
    if (tid < 80) sClsW[tid >> 3][tid & 7] = cls_w[tid];
    if (tid == 0) sFast = 1;
    __syncthreads();

    // uniform LN fast-path check (gamma == 1, beta == 0 for all stages)
    if (tid < 16) {
        const u64 one2 = 0x3f8000003f800000ull;
        int t = tid >> 2, k = tid & 3;
        if (sL1G[t][k] != one2 || sL2G[t][k] != one2 ||
            sL1B[t][k] != 0ull || sL2B[t][k] != 0ull)
            sFast = 0;
    }
    __syncthreads();

    u64 psi[8];
    {
        const float4* pp = (const float4*)(g_psi + (size_t)i * 16);
#pragma unroll
        for (int q = 0; q < 4; q++) {
            float4 v = pp[q];
            psi[2 * q] = pk(v.x, v.y);
            psi[2 * q + 1] = pk(v.z, v.w);
        }
    }

    u64 acc[4];
#pragma unroll
    for (int k = 0; k < 4; k++) acc[k] = 0ull;

    if (sFast)
        sweep<true>(sPsiP, sAttn, sFfn, sPW, sPB, sL1G, sL1B, sL2G, sL2B, psi, acc, w);
    else
        sweep<false>(sPsiP, sAttn, sFfn, sPW, sPB, sL1G, sL1B, sL2G, sL2B, psi, acc, w);

#pragma unroll
    for (int k = 0; k < 4; k++)
        up(acc[k], sRed[w][lane][2 * k], sRed[w][lane][2 * k + 1]);
    __syncthreads();
    {
        int il = tid >> 2, p = tid & 3;     // 128 threads = 32 rows x 4; 2 channels each
#pragma unroll
        for (int kk = 0; kk < 2; kk++) {
            int k = p * 2 + kk;
            float s = 0.f;
#pragma unroll
            for (int ww = 0; ww < 4; ww++) s += sRed[ww][il][k];
            sRow[il][k] = s;
        }
    }
    __syncthreads();
    {
        int il = tid >> 2, p = tid & 3;     // classifier: 32 rows x 4 threads, classes p,p+4,(p+8)
        int ii = ib * 32 + il;
        for (int c = p; c < 10; c += 4) {
            float d = 0.f;
#pragma unroll
            for (int k = 0; k < 8; k++) d += sRow[il][k] * sClsW[c][k];
            atomicAdd(&out[ii * 10 + c], d * (1.0f / BATCH));
        }
    }
}

extern "C" void kernel_launch(void* const* d_in, const int* in_sizes, int n_in,
                              void* d_out, int out_size) {
    const float* x      = (const float*)d_in[0];
    const float* proj_w = (const float*)d_in[1];
    const float* proj_b = (const float*)d_in[2];
    const float* rx     = (const float*)d_in[3];
    const float* ry     = (const float*)d_in[4];
    const float* ffn_w  = (const float*)d_in[5];
    const float* ffn_b  = (const float*)d_in[6];
    const float* ln1_g  = (const float*)d_in[7];
    const float* ln1_b  = (const float*)d_in[8];
    const float* ln2_g  = (const float*)d_in[9];
    const float* ln2_b  = (const float*)d_in[10];
    const float* cls_w  = (const float*)d_in[11];
    const float* cls_b  = (const float*)d_in[12];
    float* out = (float*)d_out;

    k_phaseB<<<128, 64>>>(x, proj_w, proj_b, rx, ry, ffn_w, ffn_b,
                          ln1_g, ln1_b, ln2_g, ln2_b, cls_b, out);
    k_final<<<dim3(32, 32), 128>>>(proj_w, proj_b, ln1_g, ln1_b, ln2_g, ln2_b,
                                   cls_w, out);
}

// round 13
// speedup vs baseline: 1.9041x; 1.0324x over previous
#include <cuda_runtime.h>

#define NB 4
#define BATCH 1024
#define EPS 1e-5f

// Scratch (no allocations allowed). 16B-aligned for vectorized access.
__device__ __align__(16) float g_psi[BATCH * 16];
__device__ __align__(16) float g_psip[BATCH * 16];
__device__ __align__(16) float g_attn[NB * BATCH * 8];   // [t][j][k]
__device__ __align__(16) float g_ffn[NB * BATCH * 8];    // [t][j][k]

// ---------------- packed f32x2 helpers ----------------
typedef unsigned long long u64;
__device__ __forceinline__ u64 pk(float lo, float hi) {
    u64 r; asm("mov.b64 %0,{%1,%2};" : "=l"(r) : "f"(lo), "f"(hi)); return r;
}
__device__ __forceinline__ void up(u64 v, float& lo, float& hi) {
    asm("mov.b64 {%0,%1},%2;" : "=f"(lo), "=f"(hi) : "l"(v));
}
__device__ __forceinline__ u64 add2(u64 a, u64 b) {
    u64 r; asm("add.rn.f32x2 %0,%1,%2;" : "=l"(r) : "l"(a), "l"(b)); return r;
}
__device__ __forceinline__ u64 mul2(u64 a, u64 b) {
    u64 r; asm("mul.rn.f32x2 %0,%1,%2;" : "=l"(r) : "l"(a), "l"(b)); return r;
}
__device__ __forceinline__ u64 fma2(u64 a, u64 b, u64 c) {
    u64 r; asm("fma.rn.f32x2 %0,%1,%2,%3;" : "=l"(r) : "l"(a), "l"(b), "l"(c)); return r;
}

// Forward CNOT-ladder permutation for n=4: (0,1),(1,2),(2,3),(3,0)
__device__ __forceinline__ int fwd4(int m) {
    int idx = m;
    idx ^= ((idx >> 3) & 1) << 2;
    idx ^= ((idx >> 2) & 1) << 1;
    idx ^= ((idx >> 1) & 1) << 0;
    idx ^= ((idx >> 0) & 1) << 3;
    return idx;
}

// LayerNorm over 8 channels; parallel sum/sumsq (var = E[h^2]-m^2), tree latency.
__device__ __forceinline__ void ln8(float h[8], const float* g, const float* b) {
    float S = ((h[0] + h[1]) + (h[2] + h[3])) + ((h[4] + h[5]) + (h[6] + h[7]));
    float q0 = h[0] * h[0], q1 = h[1] * h[1], q2 = h[2] * h[2], q3 = h[3] * h[3];
    float q4 = h[4] * h[4], q5 = h[5] * h[5], q6 = h[6] * h[6], q7 = h[7] * h[7];
    float Q = ((q0 + q1) + (q2 + q3)) + ((q4 + q5) + (q6 + q7));
    float m = S * 0.125f;
    float rs = rsqrtf(fmaf(-m, m, fmaf(Q, 0.125f, EPS)));
    float nm = -m * rs;
#pragma unroll
    for (int k = 0; k < 8; k++) {
        float t = fmaf(h[k], rs, nm);
        h[k] = fmaf(t, g[k], b[k]);
    }
}

// Packed LN for 4 columns. FAST path: gamma==1, beta==0 (verified at runtime).
template <bool FAST>
__device__ __forceinline__ void ln8p4_t(u64 h[4][4], const u64* g, const u64* b) {
    u64 rr[4], nmr[4];
#pragma unroll
    for (int q = 0; q < 4; q++) {
        u64 s = add2(add2(h[q][0], h[q][1]), add2(h[q][2], h[q][3]));
        u64 qs = mul2(h[q][0], h[q][0]);
        qs = fma2(h[q][1], h[q][1], qs);
        qs = fma2(h[q][2], h[q][2], qs);
        qs = fma2(h[q][3], h[q][3], qs);
        float sl, sh, ql, qh;
        up(s, sl, sh); up(qs, ql, qh);
        float m = (sl + sh) * 0.125f;
        float rs = rsqrtf(fmaf(-m, m, fmaf(ql + qh, 0.125f, EPS)));
        float nm = -m * rs;
        rr[q] = pk(rs, rs);
        nmr[q] = pk(nm, nm);
    }
    if (FAST) {
#pragma unroll
        for (int q = 0; q < 4; q++)
#pragma unroll
            for (int k = 0; k < 4; k++)
                h[q][k] = fma2(h[q][k], rr[q], nmr[q]);
    } else {
        ulonglong2 g01 = *(const ulonglong2*)g;
        ulonglong2 g23 = *(const ulonglong2*)(g + 2);
        ulonglong2 b01 = *(const ulonglong2*)b;
        ulonglong2 b23 = *(const ulonglong2*)(b + 2);
        u64 gr[4] = { g01.x, g01.y, g23.x, g23.y };
        u64 br[4] = { b01.x, b01.y, b23.x, b23.y };
#pragma unroll
        for (int q = 0; q < 4; q++)
#pragma unroll
            for (int k = 0; k < 4; k++) {
                u64 t = fma2(h[q][k], rr[q], nmr[q]);
                h[q][k] = fma2(t, gr[k], br[k]);
            }
    }
}

// attn[w>=1] = z0*...*zw ; attn[0] = z1*...*z7
__device__ __forceinline__ void attn8(const float z[8], float a[8]) {
    float p = z[0];
#pragma unroll
    for (int w = 1; w < 8; w++) { p *= z[w]; a[w] = p; }
    float q = z[1];
#pragma unroll
    for (int w = 2; w < 8; w++) q *= z[w];
    a[0] = q;
}

__device__ __forceinline__ void psi16(const float* __restrict__ x, int row, float p[16]) {
    float c[4], s[4];
#pragma unroll
    for (int w = 0; w < 4; w++) {
        float hh = 0.5f * x[row * 4 + w];
        c[w] = __cosf(hh); s[w] = __sinf(hh);
    }
#pragma unroll
    for (int m = 0; m < 16; m++) {
        p[m] = (((m >> 3) & 1) ? s[0] : c[0]) * (((m >> 2) & 1) ? s[1] : c[1]) *
               (((m >> 1) & 1) ? s[2] : c[2]) * (((m >> 0) & 1) ? s[3] : c[3]);
    }
}

// ---------------- Fused sequential phase (also initializes out = cls_b) ----------------
__global__ void k_phaseB(const float* __restrict__ x,
                         const float* __restrict__ proj_w, const float* __restrict__ proj_b,
                         const float* __restrict__ rx, const float* __restrict__ ry,
                         const float* __restrict__ ffn_w, const float* __restrict__ ffn_b,
                         const float* __restrict__ ln1_g, const float* __restrict__ ln1_b,
                         const float* __restrict__ ln2_g, const float* __restrict__ ln2_b,
                         const float* __restrict__ cls_b, float* __restrict__ out) {
    __shared__ float sRx[NB * 8], sRy[NB * 8];
    __shared__ float sFw[NB * 64], sFb[NB * 8];
    __shared__ float sL1G[NB * 8], sL1B[NB * 8], sL2G[NB * 8], sL2B[NB * 8];
    __shared__ float sPW[8], sPB[8];
    __shared__ float sA[NB][8][9];
    __shared__ float sF[NB][8][9];

    int tid = threadIdx.x;           // 0..63
    int gid = blockIdx.x * 64 + tid;

    // initialize classifier output with bias (k_final atomically accumulates onto it)
    for (int u = gid; u < BATCH * 10; u += 128 * 64) out[u] = cls_b[u % 10];

    if (tid < NB * 8) {
        sRx[tid] = rx[tid]; sRy[tid] = ry[tid]; sFb[tid] = ffn_b[tid];
        sL1G[tid] = ln1_g[tid]; sL1B[tid] = ln1_b[tid];
        sL2G[tid] = ln2_g[tid]; sL2B[tid] = ln2_b[tid];
    }
    if (tid < 8) { sPW[tid] = proj_w[tid]; sPB[tid] = proj_b[tid]; }
    for (int u = tid; u < NB * 64; u += 64) sFw[u] = ffn_w[u];
    __syncthreads();

    int lane = tid & 31;
    int rowbase = lane & 24;
    const unsigned mask = 0xFFFFFFFFu;

    int r0 = tid >> 3;
    int m = tid & 7;
    int j = gid >> 3;

    float pm[16];
    {
        float t16[16];
        psi16(x, m, t16);
#pragma unroll
        for (int u = 0; u < 16; u++) pm[u] = t16[fwd4(u)];
    }
    float h0[8], h1[8];
    {
        float pj[16];
        psi16(x, r0, pj);
        float d = 0.f;
#pragma unroll
        for (int u = 0; u < 16; u++) d += pj[u] * pm[u];
        float gr = fabsf(d);
#pragma unroll
        for (int k = 0; k < 8; k++) h0[k] = gr * sPW[k] + sPB[k];
    }
    {
        float pj[16];
        psi16(x, j, pj);
        float d = 0.f;
#pragma unroll
        for (int u = 0; u < 16; u++) d += pj[u] * pm[u];
        float gr = fabsf(d);
#pragma unroll
        for (int k = 0; k < 8; k++) h1[k] = gr * sPW[k] + sPB[k];

        if (m == 0) {
            float pp[16];
#pragma unroll
            for (int u = 0; u < 16; u++) pp[u] = pj[fwd4(u)];
            float4* po = (float4*)(g_psi + (size_t)j * 16);
            float4* pq = (float4*)(g_psip + (size_t)j * 16);
#pragma unroll
            for (int q = 0; q < 4; q++) {
                po[q] = make_float4(pj[4 * q], pj[4 * q + 1], pj[4 * q + 2], pj[4 * q + 3]);
                pq[q] = make_float4(pp[4 * q], pp[4 * q + 1], pp[4 * q + 2], pp[4 * q + 3]);
            }
        }
    }

    float cRx[NB], ryv[NB];
#pragma unroll
    for (int t = 0; t < NB; t++) { cRx[t] = __cosf(rx[t * 8 + m]); ryv[t] = ry[t * 8 + m]; }

#pragma unroll
    for (int t = 0; t < NB; t++) {
        float z0 = cRx[t] * __cosf(h0[0]);
        float z1 = cRx[t] * __cosf(h1[0]);
        float zz0[8], zz1[8];
#pragma unroll
        for (int u = 0; u < 8; u++) {
            zz0[u] = __shfl_sync(mask, z0, rowbase | u);
            zz1[u] = __shfl_sync(mask, z1, rowbase | u);
        }
        float a0[8], a1[8];
        attn8(zz0, a0);
        attn8(zz1, a1);
        sA[t][r0][m] = a0[m];
        g_attn[(size_t)t * BATCH * 8 + (size_t)j * 8 + m] = a1[m];
        __syncthreads();

        float av[8];
#pragma unroll
        for (int k = 0; k < 8; k++) av[k] = sA[t][m][k];
#pragma unroll
        for (int k = 0; k < 8; k++) { h0[k] += av[k]; h1[k] += av[k]; }
        ln8(h0, sL1G + t * 8, sL1B + t * 8);
        ln8(h1, sL1G + t * 8, sL1B + t * 8);

        float mv0 = __cosf(h0[0] + ryv[t]); mv0 = mv0 > 0.f ? mv0 : 0.f;
        float mv1 = __cosf(h1[0] + ryv[t]); mv1 = mv1 > 0.f ? mv1 : 0.f;
        float s0 = sFb[t * 8 + m], s1 = s0;
#pragma unroll
        for (int u = 0; u < 8; u++) {
            float w = sFw[t * 64 + m * 8 + u];
            s0 += __shfl_sync(mask, mv0, rowbase | u) * w;
            s1 += __shfl_sync(mask, mv1, rowbase | u) * w;
        }
        sF[t][r0][m] = s0;
        g_ffn[(size_t)t * BATCH * 8 + (size_t)j * 8 + m] = s1;
        __syncthreads();

        float fv[8];
#pragma unroll
        for (int k = 0; k < 8; k++) fv[k] = sF[t][m][k];
#pragma unroll
        for (int k = 0; k < 8; k++) { h0[k] += fv[k]; h1[k] += fv[k]; }
        ln8(h0, sL2G + t * 8, sL2B + t * 8);
        ln8(h1, sL2G + t * 8, sL2B + t * 8);
    }
}

// ---------------- k_final mainloop (templated on LN fast path) ----------------
// gsc[8] = precomputed |gram| for this thread's 8 columns; psi regs dead by now.
template <bool FAST>
__device__ __forceinline__ void sweep(
    const u64 (*sAttn)[32][4], const u64 (*sFfn)[32][4],
    const u64* sPW, const u64* sPB,
    const u64 (*sL1G)[4], const u64 (*sL1B)[4],
    const u64 (*sL2G)[4], const u64 (*sL2B)[4],
    const float gsc[8], u64 acc[4], int w) {
#pragma unroll
    for (int pass = 0; pass < 2; pass++) {
        int jcb = w * 8 + pass * 4;         // warp-uniform base column (4 warps x 8 cols = 32)
        u64 h[4][4];

        // h init for 4 columns (independent chains)
        {
            ulonglong2 pw01 = *(const ulonglong2*)&sPW[0];
            ulonglong2 pw23 = *(const ulonglong2*)&sPW[2];
            ulonglong2 pb01 = *(const ulonglong2*)&sPB[0];
            ulonglong2 pb23 = *(const ulonglong2*)&sPB[2];
#pragma unroll
            for (int q = 0; q < 4; q++) {
                float g = gsc[pass * 4 + q];
                u64 gg = pk(g, g);
                h[q][0] = fma2(gg, pw01.x, pb01.x);
                h[q][1] = fma2(gg, pw01.y, pb01.y);
                h[q][2] = fma2(gg, pw23.x, pb23.x);
                h[q][3] = fma2(gg, pw23.y, pb23.y);
            }
        }

#pragma unroll
        for (int t = 0; t < NB; t++) {
#pragma unroll
            for (int q = 0; q < 4; q++) {
                const u64* ap = &sAttn[t][jcb + q][0];
                ulonglong2 a01 = *(const ulonglong2*)ap;
                ulonglong2 a23 = *(const ulonglong2*)(ap + 2);
                h[q][0] = add2(h[q][0], a01.x);
                h[q][1] = add2(h[q][1], a01.y);
                h[q][2] = add2(h[q][2], a23.x);
                h[q][3] = add2(h[q][3], a23.y);
            }
            ln8p4_t<FAST>(h, sL1G[t], sL1B[t]);
#pragma unroll
            for (int q = 0; q < 4; q++) {
                const u64* fp = &sFfn[t][jcb + q][0];
                ulonglong2 f01 = *(const ulonglong2*)fp;
                ulonglong2 f23 = *(const ulonglong2*)(fp + 2);
                h[q][0] = add2(h[q][0], f01.x);
                h[q][1] = add2(h[q][1], f01.y);
                h[q][2] = add2(h[q][2], f23.x);
                h[q][3] = add2(h[q][3], f23.y);
            }
            ln8p4_t<FAST>(h, sL2G[t], sL2B[t]);
        }

#pragma unroll
        for (int k = 0; k < 4; k++)
            acc[k] = add2(acc[k], add2(add2(h[0][k], h[1][k]), add2(h[2][k], h[3][k])));
    }
}

// ---------------- Final sweep: 128-thread blocks, grid 1024, 7 blocks/SM ----------------
__global__ void __launch_bounds__(128, 7) k_final(
                        const float* __restrict__ proj_w, const float* __restrict__ proj_b,
                        const float* __restrict__ ln1_g, const float* __restrict__ ln1_b,
                        const float* __restrict__ ln2_g, const float* __restrict__ ln2_b,
                        const float* __restrict__ cls_w, float* __restrict__ out) {
    __shared__ __align__(16) u64 sPsiP[32][8];       // permuted psi, packed pairs (32 cols)
    __shared__ __align__(16) u64 sAttn[NB][32][4];
    __shared__ __align__(16) u64 sFfn[NB][32][4];
    __shared__ __align__(16) u64 sPW[4], sPB[4];
    __shared__ __align__(16) u64 sL1G[NB][4], sL1B[NB][4], sL2G[NB][4], sL2B[NB][4];
    __shared__ float sClsW[10][8];
    __shared__ float sRed[4][32][8];
    __shared__ float sRow[32][9];
    __shared__ int sFast;

    int jb = blockIdx.x;            // 32 j-blocks of 32 columns
    int ib = blockIdx.y;            // 32 i-blocks of 32 rows
    int tid = threadIdx.x;          // 128 threads = 4 warps
    int lane = tid & 31, w = tid >> 5;
    int j0 = jb * 32;
    int i = ib * 32 + lane;

    // cooperative 128-bit tile loads
    {
        const ulonglong2* gp = (const ulonglong2*)(g_psip + (size_t)j0 * 16);
        ((ulonglong2*)sPsiP)[tid] = gp[tid];                       // 128 x 16B = psip tile
        for (int u = tid; u < NB * 64; u += 128) {
            int t = u >> 6, r = u & 63;
            ((ulonglong2*)&sAttn[t][0][0])[r] =
                ((const ulonglong2*)(g_attn + (size_t)t * BATCH * 8 + j0 * 8))[r];
            ((ulonglong2*)&sFfn[t][0][0])[r] =
                ((const ulonglong2*)(g_ffn + (size_t)t * BATCH * 8 + j0 * 8))[r];
        }
    }
    if (tid < 4) { sPW[tid] = ((const u64*)proj_w)[tid]; sPB[tid] = ((const u64*)proj_b)[tid]; }
    if (tid < NB * 4) {
        int t = tid >> 2, k = tid & 3;
        sL1G[t][k] = ((const u64*)ln1_g)[tid];
        sL1B[t][k] = ((const u64*)ln1_b)[tid];
        sL2G[t][k] = ((const u64*)ln2_g)[tid];
        sL2B[t][k] = ((const u64*)ln2_b)[tid];
    }
    if (tid < 80) sClsW[tid >> 3][tid & 7] = cls_w[tid];
    if (tid == 0) sFast = 1;
    __syncthreads();

    // uniform LN fast-path check (gamma == 1, beta == 0 for all stages)
    if (tid < 16) {
        const u64 one2 = 0x3f8000003f800000ull;
        int t = tid >> 2, k = tid & 3;
        if (sL1G[t][k] != one2 || sL2G[t][k] != one2 ||
            sL1B[t][k] != 0ull || sL2B[t][k] != 0ull)
            sFast = 0;
    }
    __syncthreads();

    // Prologue: all 8 gram magnitudes for this thread's columns; psi dies here.
    float gsc[8];
    {
        u64 psi[8];
        const float4* pp = (const float4*)(g_psi + (size_t)i * 16);
#pragma unroll
        for (int q = 0; q < 4; q++) {
            float4 v = pp[q];
            psi[2 * q] = pk(v.x, v.y);
            psi[2 * q + 1] = pk(v.z, v.w);
        }
#pragma unroll
        for (int c = 0; c < 8; c++) {
            const u64* qq = &sPsiP[w * 8 + c][0];
            ulonglong2 q0 = *(const ulonglong2*)qq;
            ulonglong2 q1 = *(const ulonglong2*)(qq + 2);
            ulonglong2 q2 = *(const ulonglong2*)(qq + 4);
            ulonglong2 q3 = *(const ulonglong2*)(qq + 6);
            u64 dp = mul2(psi[0], q0.x);
            dp = fma2(psi[1], q0.y, dp);
            dp = fma2(psi[2], q1.x, dp);
            dp = fma2(psi[3], q1.y, dp);
            dp = fma2(psi[4], q2.x, dp);
            dp = fma2(psi[5], q2.y, dp);
            dp = fma2(psi[6], q3.x, dp);
            dp = fma2(psi[7], q3.y, dp);
            float dl, dh;
            up(dp, dl, dh);
            gsc[c] = fabsf(dl + dh);
        }
    }

    u64 acc[4];
#pragma unroll
    for (int k = 0; k < 4; k++) acc[k] = 0ull;

    if (sFast)
        sweep<true>(sAttn, sFfn, sPW, sPB, sL1G, sL1B, sL2G, sL2B, gsc, acc, w);
    else
        sweep<false>(sAttn, sFfn, sPW, sPB, sL1G, sL1B, sL2G, sL2B, gsc, acc, w);

#pragma unroll
    for (int k = 0; k < 4; k++)
        up(acc[k], sRed[w][lane][2 * k], sRed[w][lane][2 * k + 1]);
    __syncthreads();
    {
        int il = tid >> 2, p = tid & 3;     // 128 threads = 32 rows x 4; 2 channels each
#pragma unroll
        for (int kk = 0; kk < 2; kk++) {
            int k = p * 2 + kk;
            float s = 0.f;
#pragma unroll
            for (int ww = 0; ww < 4; ww++) s += sRed[ww][il][k];
            sRow[il][k] = s;
        }
    }
    __syncthreads();
    {
        int il = tid >> 2, p = tid & 3;     // classifier: 32 rows x 4 threads, classes p,p+4,(p+8)
        int ii = ib * 32 + il;
        for (int c = p; c < 10; c += 4) {
            float d = 0.f;
#pragma unroll
            for (int k = 0; k < 8; k++) d += sRow[il][k] * sClsW[c][k];
            atomicAdd(&out[ii * 10 + c], d * (1.0f / BATCH));
        }
    }
}

extern "C" void kernel_launch(void* const* d_in, const int* in_sizes, int n_in,
                              void* d_out, int out_size) {
    const float* x      = (const float*)d_in[0];
    const float* proj_w = (const float*)d_in[1];
    const float* proj_b = (const float*)d_in[2];
    const float* rx     = (const float*)d_in[3];
    const float* ry     = (const float*)d_in[4];
    const float* ffn_w  = (const float*)d_in[5];
    const float* ffn_b  = (const float*)d_in[6];
    const float* ln1_g  = (const float*)d_in[7];
    const float* ln1_b  = (const float*)d_in[8];
    const float* ln2_g  = (const float*)d_in[9];
    const float* ln2_b  = (const float*)d_in[10];
    const float* cls_w  = (const float*)d_in[11];
    const float* cls_b  = (const float*)d_in[12];
    float* out = (float*)d_out;

    k_phaseB<<<128, 64>>>(x, proj_w, proj_b, rx, ry, ffn_w, ffn_b,
                          ln1_g, ln1_b, ln2_g, ln2_b, cls_b, out);
    k_final<<<dim3(32, 32), 128>>>(proj_w, proj_b, ln1_g, ln1_b, ln2_g, ln2_b,
                                   cls_w, out);
}